// round 9
// baseline (speedup 1.0000x reference)
#include <cuda_runtime.h>
#include <cstdint>

// VectorQuantizer on B200 — round 9: sm_100-base tensor path via
// mma.sync.m16n8k16 bf16 + ldmatrix, with exact-fp32 candidate recheck.
// inputs:  d_in[0] = inputs  [8, 64, 32, 32, 32] fp32
//          d_in[1] = codebook [512, 64] fp32
// output:  d_out fp32 = [ quantized 16777216 | loss 1 | indices 262144 ]

#define KCODES    512
#define DCH       64
#define SPATIAL   32768
#define NVEC      262144
#define Q_ELEMS   16777216
#define LOSS_OFF  Q_ELEMS
#define IDX_OFF   (Q_ELEMS + 1)
#define TILE_M    64
#define NTILES    (NVEC / TILE_M)   // 4096
#define GRID_MAIN 148
#define BLOCK_MAIN 128
#define MARGIN    3e-3f
#define MAXCAND   16

// SMEM layout (bytes)
#define A_STRIDE   144              // 64 bf16 row padded to 144B (conflict-free ldmatrix)
#define B_STRIDE   144
#define SC_STRIDE  2064             // 516 floats per score row (4-way max on scan)
#define SM_A       0                // 64 *144  =   9216
#define SM_B       9216             // 512*144  =  73728
#define SM_SC      82944            // 64 *2064 = 132096
#define SM_SSC     215040           // 512*4    =   2048
#define SM_RED     217088           // reduction scratch (see offsets below)
#define SM_TOTAL   219648

__device__ double g_blocksums[GRID_MAIN];

__device__ __forceinline__ uint32_t smem_u32(const void* p) {
    uint32_t a;
    asm("{ .reg .u64 t; cvta.to.shared.u64 t, %1; cvt.u32.u64 %0, t; }" : "=r"(a) : "l"(p));
    return a;
}
__device__ __forceinline__ uint32_t bf16pair(float lo, float hi) {
    uint32_t r;  // packs {hi,lo} -> r = (bf16(hi)<<16)|bf16(lo)
    asm("cvt.rn.bf16x2.f32 %0, %1, %2;" : "=r"(r) : "f"(hi), "f"(lo));
    return r;
}
__device__ __forceinline__ void ldmx4(uint32_t* r, uint32_t a) {
    asm volatile("ldmatrix.sync.aligned.m8n8.x4.shared.b16 {%0,%1,%2,%3}, [%4];"
        : "=r"(r[0]), "=r"(r[1]), "=r"(r[2]), "=r"(r[3]) : "r"(a));
}
__device__ __forceinline__ void ldmx2(uint32_t* r, uint32_t a) {
    asm volatile("ldmatrix.sync.aligned.m8n8.x2.shared.b16 {%0,%1}, [%2];"
        : "=r"(r[0]), "=r"(r[1]) : "r"(a));
}
__device__ __forceinline__ void mma16816(float* d, const uint32_t* a, const uint32_t* b) {
    asm volatile("mma.sync.aligned.m16n8k16.row.col.f32.bf16.bf16.f32 "
        "{%0,%1,%2,%3}, {%4,%5,%6,%7}, {%8,%9}, {%0,%1,%2,%3};"
        : "+f"(d[0]), "+f"(d[1]), "+f"(d[2]), "+f"(d[3])
        : "r"(a[0]), "r"(a[1]), "r"(a[2]), "r"(a[3]), "r"(b[0]), "r"(b[1]));
}
__device__ __forceinline__ void sts64(uint32_t a, float x, float y) {
    asm volatile("st.shared.v2.f32 [%0], {%1,%2};" :: "r"(a), "f"(x), "f"(y) : "memory");
}
__inline__ __device__ float warpReduceSum(float v) {
    #pragma unroll
    for (int o = 16; o > 0; o >>= 1) v += __shfl_down_sync(0xffffffffu, v, o);
    return v;
}
// EXACT round-1 distance: 4 accumulators over j%4, (a0+a1)+(a2+a3), (sx+sc)-2dot
__device__ __forceinline__ float exact_d(const float* __restrict__ crow,
                                         const float (&x)[DCH], float sx, float sck) {
    float a0 = 0.f, a1 = 0.f, a2 = 0.f, a3 = 0.f;
    #pragma unroll
    for (int j = 0; j < DCH; j += 4) {
        a0 = fmaf(crow[j + 0], x[j + 0], a0);
        a1 = fmaf(crow[j + 1], x[j + 1], a1);
        a2 = fmaf(crow[j + 2], x[j + 2], a2);
        a3 = fmaf(crow[j + 3], x[j + 3], a3);
    }
    float dot = (a0 + a1) + (a2 + a3);
    return (sx + sck) - 2.0f * dot;
}

__global__ __launch_bounds__(BLOCK_MAIN, 1)
void vq_hmma(const float* __restrict__ in, const float* __restrict__ cb,
             float* __restrict__ out) {
    extern __shared__ char smem[];
    uint32_t sbase = smem_u32(smem);
    float* ssc      = (float*)(smem + SM_SSC);
    float* sminhalf = (float*)(smem + SM_RED);          // [128]
    float* sbd      = (float*)(smem + SM_RED + 512);    // [128]
    int*   sbi      = (int*)  (smem + SM_RED + 1024);   // [128]
    float* sthr     = (float*)(smem + SM_RED + 1536);   // [64]
    int*   sbidx    = (int*)  (smem + SM_RED + 1792);   // [64]
    float* swloss   = (float*)(smem + SM_RED + 2048);   // [4]

    int tid = threadIdx.x, lane = tid & 31, w = tid >> 5;
    int dv = tid & 63;      // row within tile
    int h  = tid >> 6;      // 0: cols 0-255 / j 0-31, 1: cols 256-511 / j 32-63

    // ---- codebook bf16 into SMEM B (row-major, pad 144B) ----
    const float4* cb4 = (const float4*)cb;
    for (int i = tid; i < KCODES * 16; i += BLOCK_MAIN) {
        int k = i >> 4, j4 = i & 15;
        float4 v = cb4[i];
        char* dst = smem + SM_B + k * B_STRIDE + j4 * 8;
        *(uint32_t*)(dst)     = bf16pair(v.x, v.y);
        *(uint32_t*)(dst + 4) = bf16pair(v.z, v.w);
    }
    // exact fp32 norms (reference order)
    for (int k = tid; k < KCODES; k += BLOCK_MAIN) {
        const float* c = cb + (size_t)k * DCH;
        float s = 0.f;
        #pragma unroll
        for (int j = 0; j < DCH; j++) s = fmaf(c[j], c[j], s);
        ssc[k] = s;
    }
    __syncthreads();

    float threadLoss = 0.f;

    for (int tile = blockIdx.x; tile < NTILES; tile += GRID_MAIN) {
        int v0 = tile * TILE_M;
        int b  = v0 >> 15;
        int s0 = v0 & (SPATIAL - 1);
        const float* xbase = in + (size_t)b * DCH * SPATIAL + s0 + dv;

        // ---- A fill: thread -> row dv, its 32-channel half ----
        #pragma unroll
        for (int jj = 0; jj < 32; jj += 2) {
            int j = h * 32 + jj;
            float x0 = xbase[(size_t)j * SPATIAL];
            float x1 = xbase[(size_t)(j + 1) * SPATIAL];
            *(uint32_t*)(smem + SM_A + dv * A_STRIDE + j * 2) = bf16pair(x0, x1);
        }
        __syncthreads();

        // ---- GEMM: warp w -> rows 16w..16w+15, all 512 cols ----
        uint32_t afr[4][4];
        {
            int g = lane >> 3, r = lane & 7;
            #pragma unroll
            for (int kc = 0; kc < 4; kc++) {
                uint32_t aaddr = sbase + SM_A
                    + (uint32_t)((w * 16 + r + (g & 1) * 8) * A_STRIDE)
                    + (uint32_t)((kc * 16 + (g >> 1) * 8) * 2);
                ldmx4(afr[kc], aaddr);
            }
        }
        {
            int l16 = lane & 15;
            int brow = l16 & 7, bk = (l16 >> 3) * 8;
            int qr = lane >> 2, qc = lane & 3;
            for (int nt = 0; nt < 64; nt += 2) {
                float d0[4] = {0.f, 0.f, 0.f, 0.f};
                float d1[4] = {0.f, 0.f, 0.f, 0.f};
                #pragma unroll
                for (int kc = 0; kc < 4; kc++) {
                    uint32_t b0a = sbase + SM_B
                        + (uint32_t)((nt * 8 + brow) * B_STRIDE)
                        + (uint32_t)((kc * 16 + bk) * 2);
                    uint32_t bf0[2], bf1[2];
                    ldmx2(bf0, b0a);
                    ldmx2(bf1, b0a + 8 * B_STRIDE);
                    mma16816(d0, afr[kc], bf0);
                    mma16816(d1, afr[kc], bf1);
                }
                // store raw dots: thread -> rows (16w+qr, +8), cols nt*8+2qc..(+1), +8
                uint32_t r0a = sbase + SM_SC
                    + (uint32_t)((w * 16 + qr) * SC_STRIDE)
                    + (uint32_t)((nt * 8 + qc * 2) * 4);
                uint32_t r1a = r0a + 8 * SC_STRIDE;
                sts64(r0a,      d0[0], d0[1]);
                sts64(r1a,      d0[2], d0[3]);
                sts64(r0a + 32, d1[0], d1[1]);
                sts64(r1a + 32, d1[2], d1[3]);
            }
        }
        __syncthreads();

        // ---- phase 1: per-half approx min of score = ssc[k] - 2*dot ----
        const float4* dot4 = (const float4*)(smem + SM_SC + dv * SC_STRIDE + h * 1024);
        const float4* ssc4 = (const float4*)(smem + SM_SSC + h * 1024);
        {
            float m = 3.4e38f;
            #pragma unroll 8
            for (int i = 0; i < 64; i++) {
                float4 dd = dot4[i];
                float4 ss = ssc4[i];
                m = fminf(m, fminf(fminf(ss.x - 2.f * dd.x, ss.y - 2.f * dd.y),
                                   fminf(ss.z - 2.f * dd.z, ss.w - 2.f * dd.w)));
            }
            sminhalf[tid] = m;
        }
        __syncthreads();
        if (tid < 64) sthr[tid] = fminf(sminhalf[tid], sminhalf[tid + 64]) + MARGIN;
        __syncthreads();

        // ---- phase 2: candidates (ascending k) + exact fp32 recheck ----
        {
            float thr = sthr[dv];
            int cand[MAXCAND];
            int nc = 0; bool ovf = false;
            for (int i = 0; i < 64; i++) {
                float4 dd = dot4[i];
                float4 ss = ssc4[i];
                int kb = h * 256 + i * 4;
                float e0 = ss.x - 2.f * dd.x, e1 = ss.y - 2.f * dd.y;
                float e2 = ss.z - 2.f * dd.z, e3 = ss.w - 2.f * dd.w;
                if (e0 <= thr) { if (nc < MAXCAND) cand[nc++] = kb + 0; else ovf = true; }
                if (e1 <= thr) { if (nc < MAXCAND) cand[nc++] = kb + 1; else ovf = true; }
                if (e2 <= thr) { if (nc < MAXCAND) cand[nc++] = kb + 2; else ovf = true; }
                if (e3 <= thr) { if (nc < MAXCAND) cand[nc++] = kb + 3; else ovf = true; }
            }
            float bestd = 3.4e38f; int bidx = KCODES;
            if (nc > 0 || ovf) {
                float x[DCH];
                #pragma unroll
                for (int j = 0; j < DCH; j++) x[j] = xbase[(size_t)j * SPATIAL];
                float sx = 0.f;
                #pragma unroll
                for (int j = 0; j < DCH; j++) sx = fmaf(x[j], x[j], sx);
                if (!ovf) {
                    for (int ci = 0; ci < nc; ci++) {
                        int k = cand[ci];
                        float d = exact_d(cb + (size_t)k * DCH, x, sx, ssc[k]);
                        if (d < bestd) { bestd = d; bidx = k; }
                    }
                } else {  // rare: exact scan of this half
                    for (int k = h * 256; k < h * 256 + 256; k++) {
                        float d = exact_d(cb + (size_t)k * DCH, x, sx, ssc[k]);
                        if (d < bestd) { bestd = d; bidx = k; }
                    }
                }
            }
            sbd[tid] = bestd; sbi[tid] = bidx;
        }
        __syncthreads();
        if (tid < 64) {  // combine halves; lower half (lower k) wins ties
            float dl = sbd[tid], du = sbd[tid + 64];
            int idx = (du < dl) ? sbi[tid + 64] : sbi[tid];
            sbidx[tid] = idx;
            out[IDX_OFF + v0 + tid] = (float)idx;
        }
        __syncthreads();

        // ---- epilogue: STE store x + (c - x), loss ----
        {
            int bidx = sbidx[dv];
            const float* crow = cb + (size_t)bidx * DCH;
            float* qout = out + (size_t)b * DCH * SPATIAL + s0 + dv;
            #pragma unroll
            for (int jj = 0; jj < 32; jj++) {
                int j = h * 32 + jj;
                float c  = crow[j];
                float xv = xbase[(size_t)j * SPATIAL];
                float dd = c - xv;
                qout[(size_t)j * SPATIAL] = xv + dd;  // reference STE rounding
                threadLoss = fmaf(dd, dd, threadLoss);
            }
        }
        __syncthreads();
    }

    // ---- loss reduction ----
    float ws = warpReduceSum(threadLoss);
    if (lane == 0) swloss[w] = ws;
    __syncthreads();
    if (tid == 0) {
        double t = 0.0;
        for (int i = 0; i < 4; i++) t += (double)swloss[i];
        g_blocksums[blockIdx.x] = t;
    }
}

__global__ void vq_finalize(float* __restrict__ out) {
    if (threadIdx.x == 0 && blockIdx.x == 0) {
        double t = 0.0;
        for (int i = 0; i < GRID_MAIN; i++) t += g_blocksums[i];
        out[LOSS_OFF] = (float)(1.25 * t / (double)Q_ELEMS);
    }
}

__global__ void vq_nop() {}

extern "C" void kernel_launch(void* const* d_in, const int* in_sizes, int n_in,
                              void* d_out, int out_size) {
    const float* in = (const float*)d_in[0];
    const float* cb = (const float*)d_in[1];
    float* out = (float*)d_out;

    static bool attr_set = false;
    if (!attr_set) {
        cudaFuncSetAttribute(vq_hmma, cudaFuncAttributeMaxDynamicSharedMemorySize, SM_TOTAL);
        attr_set = true;
    }

    vq_nop<<<1, 32>>>();
    vq_nop<<<1, 32>>>();
    vq_nop<<<1, 32>>>();
    vq_hmma<<<GRID_MAIN, BLOCK_MAIN, SM_TOTAL>>>(in, cb, out);
    vq_finalize<<<1, 32>>>(out);
}

// round 10
// speedup vs baseline: 1.6988x; 1.6988x over previous
#include <cuda_runtime.h>
#include <cstdint>
#include <cfloat>

// VectorQuantizer on B200 — round 10: HMMA two-pass (register scores, no SC
// buffer), x tile cached in SMEM, 2 CTAs/SM. Exact-fp32 recheck keeps indices
// bit-identical to the reference.
#define KCODES    512
#define DCH       64
#define SPATIAL   32768
#define NVEC      262144
#define Q_ELEMS   16777216
#define LOSS_OFF  Q_ELEMS
#define IDX_OFF   (Q_ELEMS + 1)
#define TILE_M    64
#define NTILES    (NVEC / TILE_M)   // 4096
#define GRID_MAIN 296               // 2 CTAs per SM
#define BLOCK_MAIN 128
#define MARGIN    3e-3f
#define MAXC      6

#define A_STRIDE   144
#define B_STRIDE   144
#define XF_STRIDE  68               // floats
#define SM_A       0                // 9216
#define SM_B       9216             // 73728
#define SM_XF      82944            // 17408
#define SM_SSC     100352           // 2048
#define SM_SXS     102400           // 256
#define SM_BIDX    102656           // 256
#define SM_LOSS    102912           // 16
#define SM_TOTAL   102944

__device__ double g_blocksums[GRID_MAIN];

__device__ __forceinline__ uint32_t smem_u32(const void* p) {
    uint32_t a;
    asm("{ .reg .u64 t; cvta.to.shared.u64 t, %1; cvt.u32.u64 %0, t; }" : "=r"(a) : "l"(p));
    return a;
}
__device__ __forceinline__ uint32_t bf16pair(float lo, float hi) {
    uint32_t r;
    asm("cvt.rn.bf16x2.f32 %0, %1, %2;" : "=r"(r) : "f"(hi), "f"(lo));
    return r;
}
__device__ __forceinline__ void ldmx4(uint32_t* r, uint32_t a) {
    asm volatile("ldmatrix.sync.aligned.m8n8.x4.shared.b16 {%0,%1,%2,%3}, [%4];"
        : "=r"(r[0]), "=r"(r[1]), "=r"(r[2]), "=r"(r[3]) : "r"(a));
}
__device__ __forceinline__ void ldmx2(uint32_t* r, uint32_t a) {
    asm volatile("ldmatrix.sync.aligned.m8n8.x2.shared.b16 {%0,%1}, [%2];"
        : "=r"(r[0]), "=r"(r[1]) : "r"(a));
}
__device__ __forceinline__ void mma16816(float* d, const uint32_t* a, const uint32_t* b) {
    asm volatile("mma.sync.aligned.m16n8k16.row.col.f32.bf16.bf16.f32 "
        "{%0,%1,%2,%3}, {%4,%5,%6,%7}, {%8,%9}, {%0,%1,%2,%3};"
        : "+f"(d[0]), "+f"(d[1]), "+f"(d[2]), "+f"(d[3])
        : "r"(a[0]), "r"(a[1]), "r"(a[2]), "r"(a[3]), "r"(b[0]), "r"(b[1]));
}
__inline__ __device__ float warpReduceSum(float v) {
    #pragma unroll
    for (int o = 16; o > 0; o >>= 1) v += __shfl_down_sync(0xffffffffu, v, o);
    return v;
}
// EXACT frozen distance: a0..a3 over j%4, (a0+a1)+(a2+a3), (sx+sc)-2dot
__device__ __forceinline__ float exact_d(const float* __restrict__ crow,
                                         const float* __restrict__ xrow,
                                         float sx, float sck) {
    float a0 = 0.f, a1 = 0.f, a2 = 0.f, a3 = 0.f;
    #pragma unroll
    for (int j = 0; j < DCH; j += 4) {
        float4 c  = *(const float4*)(crow + j);
        float4 xx = *(const float4*)(xrow + j);
        a0 = fmaf(c.x, xx.x, a0);
        a1 = fmaf(c.y, xx.y, a1);
        a2 = fmaf(c.z, xx.z, a2);
        a3 = fmaf(c.w, xx.w, a3);
    }
    return (sx + sck) - 2.0f * ((a0 + a1) + (a2 + a3));
}

__global__ __launch_bounds__(BLOCK_MAIN, 2)
void vq_hmma(const float* __restrict__ in, const float* __restrict__ cb,
             float* __restrict__ out) {
    extern __shared__ char smem[];
    uint32_t sbase = smem_u32(smem);
    float* XF    = (float*)(smem + SM_XF);
    float* ssc   = (float*)(smem + SM_SSC);
    float* sxs   = (float*)(smem + SM_SXS);
    int*   sbidx = (int*)  (smem + SM_BIDX);
    float* sloss = (float*)(smem + SM_LOSS);

    int tid = threadIdx.x, lane = tid & 31, w = tid >> 5;
    int dv = tid & 63, h = tid >> 6;           // row in tile, channel half
    int qr = lane >> 2, qc2 = (lane & 3) * 2;  // MMA D fragment coords

    // ---- codebook bf16 -> SMEM B; exact fp32 norms (reference order) ----
    const float4* cb4 = (const float4*)cb;
    for (int i = tid; i < KCODES * 16; i += BLOCK_MAIN) {
        int k = i >> 4, j4 = i & 15;
        float4 v = cb4[i];
        char* dst = smem + SM_B + k * B_STRIDE + j4 * 8;
        *(uint32_t*)(dst)     = bf16pair(v.x, v.y);
        *(uint32_t*)(dst + 4) = bf16pair(v.z, v.w);
    }
    for (int k = tid; k < KCODES; k += BLOCK_MAIN) {
        const float* c = cb + (size_t)k * DCH;
        float s = 0.f;
        #pragma unroll
        for (int j = 0; j < DCH; j++) s = fmaf(c[j], c[j], s);
        ssc[k] = s;
    }
    __syncthreads();

    float threadLoss = 0.f;

    for (int tile = blockIdx.x; tile < NTILES; tile += GRID_MAIN) {
        int v0 = tile * TILE_M;
        int b  = v0 >> 15;
        int s0 = v0 & (SPATIAL - 1);
        const float* xbase = in + (size_t)b * DCH * SPATIAL + s0 + dv;

        // ---- fill A (bf16 SW-free pad) + XF (fp32) ----
        #pragma unroll
        for (int jj = 0; jj < 32; jj += 2) {
            int j = h * 32 + jj;
            float x0 = xbase[(size_t)j * SPATIAL];
            float x1 = xbase[(size_t)(j + 1) * SPATIAL];
            *(uint32_t*)(smem + SM_A + dv * A_STRIDE + j * 2) = bf16pair(x0, x1);
            *(float2*)(XF + dv * XF_STRIDE + j) = make_float2(x0, x1);
        }
        __syncthreads();

        // sx per row: sequential j=0..63, single accumulator (frozen order)
        if (tid < TILE_M) {
            const float* xr = XF + tid * XF_STRIDE;
            float s = 0.f;
            #pragma unroll
            for (int j = 0; j < DCH; j++) s = fmaf(xr[j], xr[j], s);
            sxs[tid] = s;
        }

        // ---- A fragments (persist across both passes) ----
        uint32_t afr[4][4];
        {
            int g = lane >> 3, r = lane & 7;
            #pragma unroll
            for (int kc = 0; kc < 4; kc++) {
                uint32_t aaddr = sbase + SM_A
                    + (uint32_t)((w * 16 + r + (g & 1) * 8) * A_STRIDE)
                    + (uint32_t)((kc * 16 + (g >> 1) * 8) * 2);
                ldmx4(afr[kc], aaddr);
            }
        }
        int l16 = lane & 15;
        int brow = l16 & 7, bk = (l16 >> 3) * 8;

        // ---- pass 1: per-thread running min over its 2 rows x 128 cols ----
        float m0 = FLT_MAX, m8 = FLT_MAX;
        for (int nt = 0; nt < 64; nt += 2) {
            float d0[4] = {0.f, 0.f, 0.f, 0.f};
            float d1[4] = {0.f, 0.f, 0.f, 0.f};
            #pragma unroll
            for (int kc = 0; kc < 4; kc++) {
                uint32_t b0a = sbase + SM_B
                    + (uint32_t)((nt * 8 + brow) * B_STRIDE)
                    + (uint32_t)((kc * 16 + bk) * 2);
                uint32_t bf0[2], bf1[2];
                ldmx2(bf0, b0a);
                ldmx2(bf1, b0a + 8 * B_STRIDE);
                mma16816(d0, afr[kc], bf0);
                mma16816(d1, afr[kc], bf1);
            }
            float2 sA = *(const float2*)(ssc + nt * 8 + qc2);
            float2 sB = *(const float2*)(ssc + nt * 8 + 8 + qc2);
            m0 = fminf(m0, fminf(sA.x - 2.f * d0[0], sA.y - 2.f * d0[1]));
            m8 = fminf(m8, fminf(sA.x - 2.f * d0[2], sA.y - 2.f * d0[3]));
            m0 = fminf(m0, fminf(sB.x - 2.f * d1[0], sB.y - 2.f * d1[1]));
            m8 = fminf(m8, fminf(sB.x - 2.f * d1[2], sB.y - 2.f * d1[3]));
        }
        #pragma unroll
        for (int o = 1; o < 4; o <<= 1) {
            m0 = fminf(m0, __shfl_xor_sync(0xffffffffu, m0, o));
            m8 = fminf(m8, __shfl_xor_sync(0xffffffffu, m8, o));
        }
        float thr0 = m0 + MARGIN, thr8 = m8 + MARGIN;
        __syncthreads();   // sxs visible before exact phase

        // ---- pass 2: recompute, collect candidates, exact recheck ----
        int c0[MAXC], c8[MAXC];
        int n0 = 0, n8 = 0; bool ov0 = false, ov8 = false;
        for (int nt = 0; nt < 64; nt += 2) {
            float d0[4] = {0.f, 0.f, 0.f, 0.f};
            float d1[4] = {0.f, 0.f, 0.f, 0.f};
            #pragma unroll
            for (int kc = 0; kc < 4; kc++) {
                uint32_t b0a = sbase + SM_B
                    + (uint32_t)((nt * 8 + brow) * B_STRIDE)
                    + (uint32_t)((kc * 16 + bk) * 2);
                uint32_t bf0[2], bf1[2];
                ldmx2(bf0, b0a);
                ldmx2(bf1, b0a + 8 * B_STRIDE);
                mma16816(d0, afr[kc], bf0);
                mma16816(d1, afr[kc], bf1);
            }
            float2 sA = *(const float2*)(ssc + nt * 8 + qc2);
            float2 sB = *(const float2*)(ssc + nt * 8 + 8 + qc2);
            int kA = nt * 8 + qc2, kB = nt * 8 + 8 + qc2;
            if (sA.x - 2.f * d0[0] <= thr0) { if (n0 < MAXC) c0[n0++] = kA;     else ov0 = true; }
            if (sA.y - 2.f * d0[1] <= thr0) { if (n0 < MAXC) c0[n0++] = kA + 1; else ov0 = true; }
            if (sA.x - 2.f * d0[2] <= thr8) { if (n8 < MAXC) c8[n8++] = kA;     else ov8 = true; }
            if (sA.y - 2.f * d0[3] <= thr8) { if (n8 < MAXC) c8[n8++] = kA + 1; else ov8 = true; }
            if (sB.x - 2.f * d1[0] <= thr0) { if (n0 < MAXC) c0[n0++] = kB;     else ov0 = true; }
            if (sB.y - 2.f * d1[1] <= thr0) { if (n0 < MAXC) c0[n0++] = kB + 1; else ov0 = true; }
            if (sB.x - 2.f * d1[2] <= thr8) { if (n8 < MAXC) c8[n8++] = kB;     else ov8 = true; }
            if (sB.y - 2.f * d1[3] <= thr8) { if (n8 < MAXC) c8[n8++] = kB + 1; else ov8 = true; }
        }

        int r0 = w * 16 + qr, r8 = r0 + 8;
        const float* x0row = XF + r0 * XF_STRIDE;
        const float* x8row = XF + r8 * XF_STRIDE;
        float sx0 = sxs[r0], sx8 = sxs[r8];

        float bd0 = FLT_MAX, bd8 = FLT_MAX;
        int   bi0 = KCODES,  bi8 = KCODES;
        if (!ov0) {
            for (int ci = 0; ci < n0; ci++) {
                int k = c0[ci];
                float d = exact_d(cb + (size_t)k * DCH, x0row, sx0, ssc[k]);
                if (d < bd0) { bd0 = d; bi0 = k; }
            }
        } else {  // rare: exact scan of this thread's own 128 k's (ascending)
            for (int nt = 0; nt < 64; nt++) {
                int k = nt * 8 + qc2;
                float d = exact_d(cb + (size_t)k * DCH, x0row, sx0, ssc[k]);
                if (d < bd0) { bd0 = d; bi0 = k; }
                d = exact_d(cb + (size_t)(k + 1) * DCH, x0row, sx0, ssc[k + 1]);
                if (d < bd0) { bd0 = d; bi0 = k + 1; }
            }
        }
        if (!ov8) {
            for (int ci = 0; ci < n8; ci++) {
                int k = c8[ci];
                float d = exact_d(cb + (size_t)k * DCH, x8row, sx8, ssc[k]);
                if (d < bd8) { bd8 = d; bi8 = k; }
            }
        } else {
            for (int nt = 0; nt < 64; nt++) {
                int k = nt * 8 + qc2;
                float d = exact_d(cb + (size_t)k * DCH, x8row, sx8, ssc[k]);
                if (d < bd8) { bd8 = d; bi8 = k; }
                d = exact_d(cb + (size_t)(k + 1) * DCH, x8row, sx8, ssc[k + 1]);
                if (d < bd8) { bd8 = d; bi8 = k + 1; }
            }
        }
        // quad combine with first-min (smallest-k) tie-break
        #pragma unroll
        for (int o = 1; o < 4; o <<= 1) {
            float od = __shfl_xor_sync(0xffffffffu, bd0, o);
            int   oi = __shfl_xor_sync(0xffffffffu, bi0, o);
            if (od < bd0 || (od == bd0 && oi < bi0)) { bd0 = od; bi0 = oi; }
            od = __shfl_xor_sync(0xffffffffu, bd8, o);
            oi = __shfl_xor_sync(0xffffffffu, bi8, o);
            if (od < bd8 || (od == bd8 && oi < bi8)) { bd8 = od; bi8 = oi; }
        }
        if ((lane & 3) == 0) {
            sbidx[r0] = bi0;
            sbidx[r8] = bi8;
            out[IDX_OFF + v0 + r0] = (float)bi0;
            out[IDX_OFF + v0 + r8] = (float)bi8;
        }
        __syncthreads();

        // ---- epilogue: STE store x + (c - x) from SMEM x, loss ----
        {
            int bidx = sbidx[dv];
            const float* crow = cb + (size_t)bidx * DCH;
            const float* xr   = XF + dv * XF_STRIDE;
            float* qout = out + (size_t)b * DCH * SPATIAL + s0 + dv;
            #pragma unroll
            for (int jj = 0; jj < 32; jj++) {
                int j = h * 32 + jj;
                float c  = crow[j];
                float xv = xr[j];
                float dd = c - xv;
                qout[(size_t)j * SPATIAL] = xv + dd;   // reference STE rounding
                threadLoss = fmaf(dd, dd, threadLoss);
            }
        }
        __syncthreads();   // protect XF/A before next fill
    }

    // ---- loss reduction ----
    float ws = warpReduceSum(threadLoss);
    if (lane == 0) sloss[w] = ws;
    __syncthreads();
    if (tid == 0) {
        double t = 0.0;
        for (int i = 0; i < 4; i++) t += (double)sloss[i];
        g_blocksums[blockIdx.x] = t;
    }
}

__global__ void vq_finalize(float* __restrict__ out) {
    if (threadIdx.x == 0 && blockIdx.x == 0) {
        double t = 0.0;
        for (int i = 0; i < GRID_MAIN; i++) t += g_blocksums[i];
        out[LOSS_OFF] = (float)(1.25 * t / (double)Q_ELEMS);
    }
}

__global__ void vq_nop() {}

extern "C" void kernel_launch(void* const* d_in, const int* in_sizes, int n_in,
                              void* d_out, int out_size) {
    const float* in = (const float*)d_in[0];
    const float* cb = (const float*)d_in[1];
    float* out = (float*)d_out;

    static bool attr_set = false;
    if (!attr_set) {
        cudaFuncSetAttribute(vq_hmma, cudaFuncAttributeMaxDynamicSharedMemorySize, SM_TOTAL);
        attr_set = true;
    }

    vq_nop<<<1, 32>>>();
    vq_nop<<<1, 32>>>();
    vq_nop<<<1, 32>>>();
    vq_hmma<<<GRID_MAIN, BLOCK_MAIN, SM_TOTAL>>>(in, cb, out);
    vq_finalize<<<1, 32>>>(out);
}

// round 11
// speedup vs baseline: 1.9501x; 1.1479x over previous
#include <cuda_runtime.h>
#include <cstdint>
#include <cfloat>

// VectorQuantizer on B200 — round 11: round-10 structure + ldmatrix.x4 B loads
// (half the LDSM count) + float4 epilogue codebook reads.
#define KCODES    512
#define DCH       64
#define SPATIAL   32768
#define NVEC      262144
#define Q_ELEMS   16777216
#define LOSS_OFF  Q_ELEMS
#define IDX_OFF   (Q_ELEMS + 1)
#define TILE_M    64
#define NTILES    (NVEC / TILE_M)   // 4096
#define GRID_MAIN 296               // 2 CTAs per SM
#define BLOCK_MAIN 128
#define MARGIN    3e-3f
#define MAXC      6

#define A_STRIDE   144
#define B_STRIDE   144
#define XF_STRIDE  68               // floats
#define SM_A       0                // 9216
#define SM_B       9216             // 73728
#define SM_XF      82944            // 17408
#define SM_SSC     100352           // 2048
#define SM_SXS     102400           // 256
#define SM_BIDX    102656           // 256
#define SM_LOSS    102912           // 16
#define SM_TOTAL   102944

__device__ double g_blocksums[GRID_MAIN];

__device__ __forceinline__ uint32_t smem_u32(const void* p) {
    uint32_t a;
    asm("{ .reg .u64 t; cvta.to.shared.u64 t, %1; cvt.u32.u64 %0, t; }" : "=r"(a) : "l"(p));
    return a;
}
__device__ __forceinline__ uint32_t bf16pair(float lo, float hi) {
    uint32_t r;
    asm("cvt.rn.bf16x2.f32 %0, %1, %2;" : "=r"(r) : "f"(hi), "f"(lo));
    return r;
}
__device__ __forceinline__ void ldmx4(uint32_t* r, uint32_t a) {
    asm volatile("ldmatrix.sync.aligned.m8n8.x4.shared.b16 {%0,%1,%2,%3}, [%4];"
        : "=r"(r[0]), "=r"(r[1]), "=r"(r[2]), "=r"(r[3]) : "r"(a));
}
__device__ __forceinline__ void mma16816(float* d, const uint32_t* a, const uint32_t* b) {
    asm volatile("mma.sync.aligned.m16n8k16.row.col.f32.bf16.bf16.f32 "
        "{%0,%1,%2,%3}, {%4,%5,%6,%7}, {%8,%9}, {%0,%1,%2,%3};"
        : "+f"(d[0]), "+f"(d[1]), "+f"(d[2]), "+f"(d[3])
        : "r"(a[0]), "r"(a[1]), "r"(a[2]), "r"(a[3]), "r"(b[0]), "r"(b[1]));
}
__inline__ __device__ float warpReduceSum(float v) {
    #pragma unroll
    for (int o = 16; o > 0; o >>= 1) v += __shfl_down_sync(0xffffffffu, v, o);
    return v;
}
// EXACT frozen distance: a0..a3 over j%4, (a0+a1)+(a2+a3), (sx+sc)-2dot
__device__ __forceinline__ float exact_d(const float* __restrict__ crow,
                                         const float* __restrict__ xrow,
                                         float sx, float sck) {
    float a0 = 0.f, a1 = 0.f, a2 = 0.f, a3 = 0.f;
    #pragma unroll
    for (int j = 0; j < DCH; j += 4) {
        float4 c  = *(const float4*)(crow + j);
        float4 xx = *(const float4*)(xrow + j);
        a0 = fmaf(c.x, xx.x, a0);
        a1 = fmaf(c.y, xx.y, a1);
        a2 = fmaf(c.z, xx.z, a2);
        a3 = fmaf(c.w, xx.w, a3);
    }
    return (sx + sck) - 2.0f * ((a0 + a1) + (a2 + a3));
}

__global__ __launch_bounds__(BLOCK_MAIN, 2)
void vq_hmma(const float* __restrict__ in, const float* __restrict__ cb,
             float* __restrict__ out) {
    extern __shared__ char smem[];
    uint32_t sbase = smem_u32(smem);
    float* XF    = (float*)(smem + SM_XF);
    float* ssc   = (float*)(smem + SM_SSC);
    float* sxs   = (float*)(smem + SM_SXS);
    int*   sbidx = (int*)  (smem + SM_BIDX);
    float* sloss = (float*)(smem + SM_LOSS);

    int tid = threadIdx.x, lane = tid & 31, w = tid >> 5;
    int dv = tid & 63, h = tid >> 6;           // row in tile, channel half
    int qr = lane >> 2, qc2 = (lane & 3) * 2;  // MMA D fragment coords

    // ---- codebook bf16 -> SMEM B; exact fp32 norms (reference order) ----
    const float4* cb4 = (const float4*)cb;
    for (int i = tid; i < KCODES * 16; i += BLOCK_MAIN) {
        int k = i >> 4, j4 = i & 15;
        float4 v = cb4[i];
        char* dst = smem + SM_B + k * B_STRIDE + j4 * 8;
        *(uint32_t*)(dst)     = bf16pair(v.x, v.y);
        *(uint32_t*)(dst + 4) = bf16pair(v.z, v.w);
    }
    for (int k = tid; k < KCODES; k += BLOCK_MAIN) {
        const float* c = cb + (size_t)k * DCH;
        float s = 0.f;
        #pragma unroll
        for (int j = 0; j < DCH; j++) s = fmaf(c[j], c[j], s);
        ssc[k] = s;
    }
    __syncthreads();

    float threadLoss = 0.f;

    for (int tile = blockIdx.x; tile < NTILES; tile += GRID_MAIN) {
        int v0 = tile * TILE_M;
        int b  = v0 >> 15;
        int s0 = v0 & (SPATIAL - 1);
        const float* xbase = in + (size_t)b * DCH * SPATIAL + s0 + dv;

        // ---- fill A (bf16) + XF (fp32) ----
        #pragma unroll
        for (int jj = 0; jj < 32; jj += 2) {
            int j = h * 32 + jj;
            float x0 = xbase[(size_t)j * SPATIAL];
            float x1 = xbase[(size_t)(j + 1) * SPATIAL];
            *(uint32_t*)(smem + SM_A + dv * A_STRIDE + j * 2) = bf16pair(x0, x1);
            *(float2*)(XF + dv * XF_STRIDE + j) = make_float2(x0, x1);
        }
        __syncthreads();

        // sx per row: sequential j=0..63, single accumulator (frozen order)
        if (tid < TILE_M) {
            const float* xr = XF + tid * XF_STRIDE;
            float s = 0.f;
            #pragma unroll
            for (int j = 0; j < DCH; j++) s = fmaf(xr[j], xr[j], s);
            sxs[tid] = s;
        }

        // ---- A fragments (persist across both passes) ----
        uint32_t afr[4][4];
        int g = lane >> 3, r = lane & 7;
        {
            #pragma unroll
            for (int kc = 0; kc < 4; kc++) {
                uint32_t aaddr = sbase + SM_A
                    + (uint32_t)((w * 16 + r + (g & 1) * 8) * A_STRIDE)
                    + (uint32_t)((kc * 16 + (g >> 1) * 8) * 2);
                ldmx4(afr[kc], aaddr);
            }
        }
        // B ldmx4 base: matrices 0,1 = n-rows nt*8..+7 (k halves), 2,3 = +8 rows
        uint32_t bbase = sbase + SM_B
            + (uint32_t)(((g >> 1) * 8 + r) * B_STRIDE)
            + (uint32_t)((g & 1) * 16);

        // ---- pass 1: per-thread running min over its 2 rows x 128 cols ----
        float m0 = FLT_MAX, m8 = FLT_MAX;
        for (int nt = 0; nt < 64; nt += 2) {
            float d0[4] = {0.f, 0.f, 0.f, 0.f};
            float d1[4] = {0.f, 0.f, 0.f, 0.f};
            uint32_t brow = bbase + (uint32_t)(nt * 8 * B_STRIDE);
            #pragma unroll
            for (int kc = 0; kc < 4; kc++) {
                uint32_t bf[4];
                ldmx4(bf, brow + kc * 32);
                mma16816(d0, afr[kc], bf + 0);
                mma16816(d1, afr[kc], bf + 2);
            }
            float2 sA = *(const float2*)(ssc + nt * 8 + qc2);
            float2 sB = *(const float2*)(ssc + nt * 8 + 8 + qc2);
            m0 = fminf(m0, fminf(sA.x - 2.f * d0[0], sA.y - 2.f * d0[1]));
            m8 = fminf(m8, fminf(sA.x - 2.f * d0[2], sA.y - 2.f * d0[3]));
            m0 = fminf(m0, fminf(sB.x - 2.f * d1[0], sB.y - 2.f * d1[1]));
            m8 = fminf(m8, fminf(sB.x - 2.f * d1[2], sB.y - 2.f * d1[3]));
        }
        #pragma unroll
        for (int o = 1; o < 4; o <<= 1) {
            m0 = fminf(m0, __shfl_xor_sync(0xffffffffu, m0, o));
            m8 = fminf(m8, __shfl_xor_sync(0xffffffffu, m8, o));
        }
        float thr0 = m0 + MARGIN, thr8 = m8 + MARGIN;
        __syncthreads();   // sxs visible before exact phase

        // ---- pass 2: recompute, collect candidates, exact recheck ----
        int c0[MAXC], c8[MAXC];
        int n0 = 0, n8 = 0; bool ov0 = false, ov8 = false;
        for (int nt = 0; nt < 64; nt += 2) {
            float d0[4] = {0.f, 0.f, 0.f, 0.f};
            float d1[4] = {0.f, 0.f, 0.f, 0.f};
            uint32_t brow = bbase + (uint32_t)(nt * 8 * B_STRIDE);
            #pragma unroll
            for (int kc = 0; kc < 4; kc++) {
                uint32_t bf[4];
                ldmx4(bf, brow + kc * 32);
                mma16816(d0, afr[kc], bf + 0);
                mma16816(d1, afr[kc], bf + 2);
            }
            float2 sA = *(const float2*)(ssc + nt * 8 + qc2);
            float2 sB = *(const float2*)(ssc + nt * 8 + 8 + qc2);
            int kA = nt * 8 + qc2, kB = nt * 8 + 8 + qc2;
            if (sA.x - 2.f * d0[0] <= thr0) { if (n0 < MAXC) c0[n0++] = kA;     else ov0 = true; }
            if (sA.y - 2.f * d0[1] <= thr0) { if (n0 < MAXC) c0[n0++] = kA + 1; else ov0 = true; }
            if (sA.x - 2.f * d0[2] <= thr8) { if (n8 < MAXC) c8[n8++] = kA;     else ov8 = true; }
            if (sA.y - 2.f * d0[3] <= thr8) { if (n8 < MAXC) c8[n8++] = kA + 1; else ov8 = true; }
            if (sB.x - 2.f * d1[0] <= thr0) { if (n0 < MAXC) c0[n0++] = kB;     else ov0 = true; }
            if (sB.y - 2.f * d1[1] <= thr0) { if (n0 < MAXC) c0[n0++] = kB + 1; else ov0 = true; }
            if (sB.x - 2.f * d1[2] <= thr8) { if (n8 < MAXC) c8[n8++] = kB;     else ov8 = true; }
            if (sB.y - 2.f * d1[3] <= thr8) { if (n8 < MAXC) c8[n8++] = kB + 1; else ov8 = true; }
        }

        int r0 = w * 16 + qr, r8 = r0 + 8;
        const float* x0row = XF + r0 * XF_STRIDE;
        const float* x8row = XF + r8 * XF_STRIDE;
        float sx0 = sxs[r0], sx8 = sxs[r8];

        float bd0 = FLT_MAX, bd8 = FLT_MAX;
        int   bi0 = KCODES,  bi8 = KCODES;
        if (!ov0) {
            for (int ci = 0; ci < n0; ci++) {
                int k = c0[ci];
                float d = exact_d(cb + (size_t)k * DCH, x0row, sx0, ssc[k]);
                if (d < bd0) { bd0 = d; bi0 = k; }
            }
        } else {  // rare: exact scan of this thread's own 128 k's (ascending)
            for (int nt = 0; nt < 64; nt++) {
                int k = nt * 8 + qc2;
                float d = exact_d(cb + (size_t)k * DCH, x0row, sx0, ssc[k]);
                if (d < bd0) { bd0 = d; bi0 = k; }
                d = exact_d(cb + (size_t)(k + 1) * DCH, x0row, sx0, ssc[k + 1]);
                if (d < bd0) { bd0 = d; bi0 = k + 1; }
            }
        }
        if (!ov8) {
            for (int ci = 0; ci < n8; ci++) {
                int k = c8[ci];
                float d = exact_d(cb + (size_t)k * DCH, x8row, sx8, ssc[k]);
                if (d < bd8) { bd8 = d; bi8 = k; }
            }
        } else {
            for (int nt = 0; nt < 64; nt++) {
                int k = nt * 8 + qc2;
                float d = exact_d(cb + (size_t)k * DCH, x8row, sx8, ssc[k]);
                if (d < bd8) { bd8 = d; bi8 = k; }
                d = exact_d(cb + (size_t)(k + 1) * DCH, x8row, sx8, ssc[k + 1]);
                if (d < bd8) { bd8 = d; bi8 = k + 1; }
            }
        }
        // quad combine with first-min (smallest-k) tie-break
        #pragma unroll
        for (int o = 1; o < 4; o <<= 1) {
            float od = __shfl_xor_sync(0xffffffffu, bd0, o);
            int   oi = __shfl_xor_sync(0xffffffffu, bi0, o);
            if (od < bd0 || (od == bd0 && oi < bi0)) { bd0 = od; bi0 = oi; }
            od = __shfl_xor_sync(0xffffffffu, bd8, o);
            oi = __shfl_xor_sync(0xffffffffu, bi8, o);
            if (od < bd8 || (od == bd8 && oi < bi8)) { bd8 = od; bi8 = oi; }
        }
        if ((lane & 3) == 0) {
            sbidx[r0] = bi0;
            sbidx[r8] = bi8;
            out[IDX_OFF + v0 + r0] = (float)bi0;
            out[IDX_OFF + v0 + r8] = (float)bi8;
        }
        __syncthreads();

        // ---- epilogue: STE store x + (c - x); cb rows via float4 ----
        {
            int bidx = sbidx[dv];
            const float* crow = cb + (size_t)bidx * DCH + h * 32;
            const float* xr   = XF + dv * XF_STRIDE + h * 32;
            float* qout = out + (size_t)b * DCH * SPATIAL + s0 + dv
                        + (size_t)h * 32 * SPATIAL;
            #pragma unroll
            for (int q4 = 0; q4 < 8; q4++) {
                float4 c  = *(const float4*)(crow + q4 * 4);
                float4 xv = *(const float4*)(xr + q4 * 4);
                float dd;
                dd = c.x - xv.x; qout[(size_t)(q4 * 4 + 0) * SPATIAL] = xv.x + dd;
                threadLoss = fmaf(dd, dd, threadLoss);
                dd = c.y - xv.y; qout[(size_t)(q4 * 4 + 1) * SPATIAL] = xv.y + dd;
                threadLoss = fmaf(dd, dd, threadLoss);
                dd = c.z - xv.z; qout[(size_t)(q4 * 4 + 2) * SPATIAL] = xv.z + dd;
                threadLoss = fmaf(dd, dd, threadLoss);
                dd = c.w - xv.w; qout[(size_t)(q4 * 4 + 3) * SPATIAL] = xv.w + dd;
                threadLoss = fmaf(dd, dd, threadLoss);
            }
        }
        __syncthreads();   // protect XF/A before next fill
    }

    // ---- loss reduction ----
    float ws = warpReduceSum(threadLoss);
    if (lane == 0) sloss[w] = ws;
    __syncthreads();
    if (tid == 0) {
        double t = 0.0;
        for (int i = 0; i < 4; i++) t += (double)sloss[i];
        g_blocksums[blockIdx.x] = t;
    }
}

__global__ void vq_finalize(float* __restrict__ out) {
    if (threadIdx.x == 0 && blockIdx.x == 0) {
        double t = 0.0;
        for (int i = 0; i < GRID_MAIN; i++) t += g_blocksums[i];
        out[LOSS_OFF] = (float)(1.25 * t / (double)Q_ELEMS);
    }
}

__global__ void vq_nop() {}

extern "C" void kernel_launch(void* const* d_in, const int* in_sizes, int n_in,
                              void* d_out, int out_size) {
    const float* in = (const float*)d_in[0];
    const float* cb = (const float*)d_in[1];
    float* out = (float*)d_out;

    static bool attr_set = false;
    if (!attr_set) {
        cudaFuncSetAttribute(vq_hmma, cudaFuncAttributeMaxDynamicSharedMemorySize, SM_TOTAL);
        attr_set = true;
    }

    vq_nop<<<1, 32>>>();
    vq_nop<<<1, 32>>>();
    vq_nop<<<1, 32>>>();
    vq_hmma<<<GRID_MAIN, BLOCK_MAIN, SM_TOTAL>>>(in, cb, out);
    vq_finalize<<<1, 32>>>(out);
}